// round 15
// baseline (speedup 1.0000x reference)
#include <cuda_runtime.h>
#include <cuda_bf16.h>
#include <cstdint>

// ---------------------------------------------------------------------------
// SpikeLinear: out = x @ W^T + bias, then LIF scan (T=16), fully fused.
//
// Round 15: last untested matrix cell — R10 structure (BK=16, 4-stage ring,
// 1 sync / 2 iters, occ 2) + 'tot' panel accumulators in per-thread-private
// shared slots. R10 at regs=128 leaves ptxas NO headroom to hoist the k+1
// LDS group above the k-step FMAs (fma pipe idles 8% of slots). Freeing 32
// regs at occ 2 (unlike R11's occ-3 variant, which capped regs at 80 and
// split smem 3 ways) gives the scheduler room to pipeline shared loads.
//
// Arithmetic bitwise-identical to rounds 4-14 (Eigen kc=248 panel
// replication via fma.rn.f32x2, rel_err 0.000970705): ascending-k fmaf per
// panel, folds at k_end = 248/496/744/992/1024, + bias, ascending-t LIF.
// ---------------------------------------------------------------------------

#define KC 248               // Eigen panel width (validated round 4)

#define BM 128
#define BN 64
#define BK 16
#define TN 4
#define T_STEPS 16
#define NACC 16              // 4 m-pairs x 4 n per thread

#define STAGE_FLOATS (BK * (BM + BN))          // 3072 floats = 12 KB
#define RING_BYTES   (4 * STAGE_FLOATS * 4)    // 48 KB
#define TOT_BYTES    (NACC * 256 * 8)          // 32 KB
#define SMEM_BYTES   (RING_BYTES + TOT_BYTES)  // 80 KB (x2 blocks = 160 KB/SM)

#define FMA_F32X2(d, a, b, c) \
    asm("fma.rn.f32x2 %0, %1, %2, %3;" : "=l"(d) : "l"(a), "l"(b), "l"(c))
#define ADD_F32X2_(d, a, b) \
    asm("add.rn.f32x2 %0, %1, %2;" : "=l"(d) : "l"(a), "l"(b))
#define PACK_DUP_F32(d, x) \
    asm("mov.b64 %0, {%1, %2};" : "=l"(d) : "f"(x), "f"(x))
#define UNPACK_F32X2_(lo, hi, p) \
    asm("mov.b64 {%0, %1}, %2;" : "=f"(lo), "=f"(hi) : "l"(p))

__global__ __launch_bounds__(256, 2)
void spikelinear_fused_kernel(const float* __restrict__ A,
                              const float* __restrict__ W,
                              const float* __restrict__ bias,
                              float* __restrict__ spikes,
                              int B, int N, int K) {
    extern __shared__ float smem[];
    float* const st0 = smem + 0 * STAGE_FLOATS;
    float* const st1 = smem + 1 * STAGE_FLOATS;
    float* const st2 = smem + 2 * STAGE_FLOATS;
    float* const st3 = smem + 3 * STAGE_FLOATS;
    unsigned long long* const tot_s =
        reinterpret_cast<unsigned long long*>(smem + 4 * STAGE_FLOATS);

    const int tid    = threadIdx.x;          // 0..255
    const int b_tile = blockIdx.y;            // batch tile (8 b's)
    const int bcol   = blockIdx.x;            // N tile

    const int tcol = tid % (BN / TN);          // 0..15
    const int trow = tid / (BN / TN);          // 0..15

    const int b_base = b_tile * (BM / T_STEPS);   // 8 b's per block

    // panel accumulator in registers; folded totals in shared (private slot)
    unsigned long long cur[4][TN];
    #pragma unroll
    for (int i = 0; i < 4; i++)
        #pragma unroll
        for (int j = 0; j < TN; j++) cur[i][j] = 0ull;

    #pragma unroll
    for (int idx = 0; idx < NACC; idx++)
        tot_s[idx * 256 + tid] = 0ull;       // private: no sync needed

    const float* Wb = W + (size_t)bcol * BN * K;

    // loader mapping (BK=16): A tile 128x16 -> 2 float4/thread,
    // W tile 64x16 -> 1 float4/thread.
    const int ld_row = tid / 4;               // 0..63
    const int ld_col = (tid % 4) * 4;         // 0,4,8,12

    // tile_row -> global m: b_local = row>>4, t = row&15, m = t*B + b_base + b_local
    const int tr0 = ld_row;
    const int tr1 = ld_row + 64;
    const float* rowA0 = A + (size_t)((tr0 & 15) * B + b_base + (tr0 >> 4)) * K;
    const float* rowA1 = A + (size_t)((tr1 & 15) * B + b_base + (tr1 >> 4)) * K;
    const float* rowW  = Wb + (size_t)ld_row * K;

    float4 rA0, rA1, rW;

    // STS of the register-held tile into stage S
#define STS_TILE(S)                                                         \
    {                                                                       \
        float* as_ = (S);                                                   \
        float* ws_ = (S) + BK * BM;                                         \
        as_[(ld_col + 0) * BM + tr0] = rA0.x;                               \
        as_[(ld_col + 1) * BM + tr0] = rA0.y;                               \
        as_[(ld_col + 2) * BM + tr0] = rA0.z;                               \
        as_[(ld_col + 3) * BM + tr0] = rA0.w;                               \
        as_[(ld_col + 0) * BM + tr1] = rA1.x;                               \
        as_[(ld_col + 1) * BM + tr1] = rA1.y;                               \
        as_[(ld_col + 2) * BM + tr1] = rA1.z;                               \
        as_[(ld_col + 3) * BM + tr1] = rA1.w;                               \
        ws_[(ld_col + 0) * BN + ld_row] = rW.x;                             \
        ws_[(ld_col + 1) * BN + ld_row] = rW.y;                             \
        ws_[(ld_col + 2) * BN + ld_row] = rW.z;                             \
        ws_[(ld_col + 3) * BN + ld_row] = rW.w;                             \
    }

    // one GEMM iteration: prefetch tile I+2, compute stage CUR, STS -> NXT
#define GEMM_ITER(I, CUR, NXT)                                              \
    {                                                                       \
        const int k0_ = (I) * BK;                                           \
        const bool has_pf_ = (I) + 2 < niter;                               \
        if (has_pf_) {                                                      \
            const int kn_ = ((I) + 2) * BK + ld_col;                        \
            rA0 = *reinterpret_cast<const float4*>(rowA0 + kn_);            \
            rA1 = *reinterpret_cast<const float4*>(rowA1 + kn_);            \
            rW  = *reinterpret_cast<const float4*>(rowW + kn_);             \
        }                                                                   \
        int fold_local_ = -1;                                               \
        {                                                                   \
            int next_b_ = ((k0_ / KC) + 1) * KC;                            \
            if (next_b_ <= k0_ + BK)      fold_local_ = next_b_ - k0_ - 1;  \
            else if (k0_ + BK == K)       fold_local_ = BK - 1;             \
        }                                                                   \
        const float* as_ = (CUR);                                           \
        const float* ws_ = (CUR) + BK * BM;                                 \
        _Pragma("unroll")                                                   \
        for (int k = 0; k < BK; k++) {                                      \
            const ulonglong2* As2_ = reinterpret_cast<const ulonglong2*>(   \
                as_ + k * BM + trow * 8);                                   \
            ulonglong2 al_ = As2_[0];                                       \
            ulonglong2 ah_ = As2_[1];                                       \
            unsigned long long ap_[4] = {al_.x, al_.y, ah_.x, ah_.y};       \
            const float4* Ws4_ =                                            \
                reinterpret_cast<const float4*>(ws_ + k * BN);              \
            float4 w_ = Ws4_[tcol];                                         \
            unsigned long long wp_[TN];                                     \
            PACK_DUP_F32(wp_[0], w_.x);                                     \
            PACK_DUP_F32(wp_[1], w_.y);                                     \
            PACK_DUP_F32(wp_[2], w_.z);                                     \
            PACK_DUP_F32(wp_[3], w_.w);                                     \
            _Pragma("unroll")                                               \
            for (int i = 0; i < 4; i++)                                     \
                _Pragma("unroll")                                           \
                for (int j = 0; j < TN; j++)                                \
                    FMA_F32X2(cur[i][j], ap_[i], wp_[j], cur[i][j]);        \
            if (k == fold_local_) {                                         \
                _Pragma("unroll")                                           \
                for (int i = 0; i < 4; i++)                                 \
                    _Pragma("unroll")                                       \
                    for (int j = 0; j < TN; j++) {                          \
                        const int idx_ = i * TN + j;                        \
                        unsigned long long t_ = tot_s[idx_ * 256 + tid];    \
                        ADD_F32X2_(t_, t_, cur[i][j]);                      \
                        tot_s[idx_ * 256 + tid] = t_;                       \
                        cur[i][j] = 0ull;                                   \
                    }                                                       \
            }                                                               \
        }                                                                   \
        if (has_pf_) STS_TILE(NXT);                                         \
    }

    const int niter = K / BK;   // 64

    // ---- prologue: fill stages 0 and 1 ----
    rA0 = *reinterpret_cast<const float4*>(rowA0 + ld_col);
    rA1 = *reinterpret_cast<const float4*>(rowA1 + ld_col);
    rW  = *reinterpret_cast<const float4*>(rowW + ld_col);
    STS_TILE(st0);
    rA0 = *reinterpret_cast<const float4*>(rowA0 + BK + ld_col);
    rA1 = *reinterpret_cast<const float4*>(rowA1 + BK + ld_col);
    rW  = *reinterpret_cast<const float4*>(rowW + BK + ld_col);
    STS_TILE(st1);
    __syncthreads();

    // ---- main loop: 4-stage ring, sync after every odd iteration ----
    for (int i = 0; i < niter; i += 4) {
        GEMM_ITER(i + 0, st0, st2);
        GEMM_ITER(i + 1, st1, st3);
        __syncthreads();
        GEMM_ITER(i + 2, st2, st0);
        GEMM_ITER(i + 3, st3, st1);
        __syncthreads();
    }

    // ------------------------- fused epilogue -------------------------
    // thread rows: tile rows trow*8 + r (r=0..7)
    //   b_local = trow>>1, t = (trow&1)*8 + r
    const int n0 = bcol * BN + tcol * TN;
    const int b  = b_base + (trow >> 1);
    const bool upper = (trow & 1);

    // unpack tot (from shared) + bias (identical scalar fp32 add)
    float v[8][TN];
    #pragma unroll
    for (int i = 0; i < 4; i++) {
        #pragma unroll
        for (int j = 0; j < TN; j++) {
            unsigned long long t = tot_s[(i * TN + j) * 256 + tid];
            float lo, hi;
            UNPACK_F32X2_(lo, hi, t);
            v[2 * i + 0][j] = lo + bias[n0 + j];
            v[2 * i + 1][j] = hi + bias[n0 + j];
        }
    }

    // LIF scan, ascending t. Pass 1: scan from 0 (valid for lower half).
    float sp[8][TN];
    float fin[TN];
    #pragma unroll
    for (int j = 0; j < TN; j++) {
        float memb = 0.0f;
        #pragma unroll
        for (int r = 0; r < 8; r++) {
            memb += v[r][j];
            float s = (memb > 1.0f) ? 1.0f : 0.0f;
            sp[r][j] = s;
            memb = (s > 0.0f) ? 0.0f : memb;
        }
        fin[j] = memb;
    }
    // hand membrane from lower half (lane l) to upper half (lane l+16)
    #pragma unroll
    for (int j = 0; j < TN; j++)
        fin[j] = __shfl_up_sync(0xffffffffu, fin[j], 16);
    if (upper) {
        #pragma unroll
        for (int j = 0; j < TN; j++) {
            float memb = fin[j];
            #pragma unroll
            for (int r = 0; r < 8; r++) {
                memb += v[r][j];
                float s = (memb > 1.0f) ? 1.0f : 0.0f;
                sp[r][j] = s;
                memb = (s > 0.0f) ? 0.0f : memb;
            }
        }
    }

    // store spikes: row m = t*B + b, t = upper*8 + r
    #pragma unroll
    for (int r = 0; r < 8; r++) {
        const int t = (upper ? 8 : 0) + r;
        float* crow = spikes + (size_t)(t * B + b) * N + n0;
        float4 o;
        o.x = sp[r][0];
        o.y = sp[r][1];
        o.z = sp[r][2];
        o.w = sp[r][3];
        *reinterpret_cast<float4*>(crow) = o;
    }
}

// ----------------------------- launch --------------------------------------
extern "C" void kernel_launch(void* const* d_in, const int* in_sizes, int n_in,
                              void* d_out, int out_size) {
    const float* x    = (const float*)d_in[0];  // [T*B, F_IN]
    const float* w    = (const float*)d_in[1];  // [F_OUT, F_IN]
    const float* bias = (const float*)d_in[2];  // [F_OUT]

    const int F_OUT = in_sizes[2];                 // 1024
    const int F_IN  = in_sizes[1] / F_OUT;         // 1024
    const int M     = in_sizes[0] / F_IN;          // 32768
    const int B     = M / T_STEPS;                 // 2048

    cudaFuncSetAttribute(spikelinear_fused_kernel,
                         cudaFuncAttributeMaxDynamicSharedMemorySize,
                         SMEM_BYTES);

    dim3 grid(F_OUT / BN, B / (BM / T_STEPS));     // (16, 256)
    spikelinear_fused_kernel<<<grid, 256, SMEM_BYTES>>>(x, w, bias,
                                                        (float*)d_out,
                                                        B, F_OUT, F_IN);
}

// round 16
// speedup vs baseline: 1.0513x; 1.0513x over previous
#include <cuda_runtime.h>
#include <cuda_bf16.h>
#include <cstdint>

// ---------------------------------------------------------------------------
// SpikeLinear: out = x @ W^T + bias, then LIF scan (T=16), fully fused.
//
// FINAL KERNEL (rounds 10/13/14: 1437.8 / 1438.2 / 1439.3 us; ~95% of the
// FFMA2 rt=3 issue floor of ~1363 us @ 2.0 GHz NAT).
//
// Design decisions, each validated by an isolated experiment:
//  - Numerics: replicate the reference's XLA:CPU/Eigen gebp accumulation
//    (kc=248 panel restart, ascending-k fmaf, ascending panel folds at
//    k_end = 248/496/744/992/1024, fp32 bias add, ascending-t LIF scan)
//    -> rel_err 0.000970705, bit-stable across 12 benches. ANY reordering
//    (tensor cores, exact fp64 accumulation) decorrelates the binary spike
//    flips from the reference and fails the 1e-3 threshold (rounds 1-3).
//  - fma.rn.f32x2 (FFMA2): 2 IEEE fp32 RN FMAs/instr, bit-identical per
//    component, ptxas never auto-emits it. rt=3 from RF banking (3 distinct
//    64-bit operand pairs) => 85.3 FMA/cyc/SM floor (round 5).
//  - BK=16, 4-stage smem ring, one __syncthreads per 2 iterations
//    (rounds 6/8/9/10: BK=32 regresses ~20% via LDG/STS burst serialization;
//    further barrier reduction gains only ~2.5 us).
//  - LIF scan fused into the GEMM epilogue via t-major M-tile remap +
//    half-warp shuffle handoff (round 7: -37 us, kills the 256 MB
//    intermediate round-trip).
//  - W stays fp32 in shared; {w,w} packs ride the ~90%-idle ALU pipe
//    (round 12: pre-duplicated u64 W doubles LDS wavefronts and saturates
//    the 128 B/cyc smem crossbar -> 2x regression).
//  - Accumulators in registers at occ 2 (round 11: occ 3 net worse;
//    round 15: tot-in-shared at occ 2 net worse, -5%).
// ---------------------------------------------------------------------------

#define KC 248               // Eigen panel width (validated round 4)

#define BM 128
#define BN 64
#define BK 16
#define TN 4
#define T_STEPS 16

#define STAGE_FLOATS (BK * (BM + BN))          // 3072 floats = 12 KB
#define SMEM_BYTES   (4 * STAGE_FLOATS * 4)    // 48 KB

#define FMA_F32X2(d, a, b, c) \
    asm("fma.rn.f32x2 %0, %1, %2, %3;" : "=l"(d) : "l"(a), "l"(b), "l"(c))
#define ADD_F32X2_(d, a, b) \
    asm("add.rn.f32x2 %0, %1, %2;" : "=l"(d) : "l"(a), "l"(b))
#define PACK_DUP_F32(d, x) \
    asm("mov.b64 %0, {%1, %2};" : "=l"(d) : "f"(x), "f"(x))
#define UNPACK_F32X2_(lo, hi, p) \
    asm("mov.b64 {%0, %1}, %2;" : "=f"(lo), "=f"(hi) : "l"(p))

__global__ __launch_bounds__(256, 2)
void spikelinear_fused_kernel(const float* __restrict__ A,
                              const float* __restrict__ W,
                              const float* __restrict__ bias,
                              float* __restrict__ spikes,
                              int B, int N, int K) {
    extern __shared__ float smem[];
    // stage s: As = smem + s*STAGE_FLOATS            ([BK][BM])
    //          Ws = smem + s*STAGE_FLOATS + BK*BM    ([BK][BN])
    float* const st0 = smem + 0 * STAGE_FLOATS;
    float* const st1 = smem + 1 * STAGE_FLOATS;
    float* const st2 = smem + 2 * STAGE_FLOATS;
    float* const st3 = smem + 3 * STAGE_FLOATS;

    const int tid    = threadIdx.x;          // 0..255
    const int b_tile = blockIdx.y;            // batch tile (8 b's)
    const int bcol   = blockIdx.x;            // N tile

    const int tcol = tid % (BN / TN);          // 0..15
    const int trow = tid / (BN / TN);          // 0..15

    const int b_base = b_tile * (BM / T_STEPS);   // 8 b's per block

    // packed accumulators: [m-pair 0..3][n 0..3]
    unsigned long long cur[4][TN];
    unsigned long long tot[4][TN];
    #pragma unroll
    for (int i = 0; i < 4; i++)
        #pragma unroll
        for (int j = 0; j < TN; j++) { cur[i][j] = 0ull; tot[i][j] = 0ull; }

    const float* Wb = W + (size_t)bcol * BN * K;

    // loader mapping (BK=16): A tile 128x16 -> 2 float4/thread,
    // W tile 64x16 -> 1 float4/thread.
    const int ld_row = tid / 4;               // 0..63
    const int ld_col = (tid % 4) * 4;         // 0,4,8,12

    // tile_row -> global m: b_local = row>>4, t = row&15, m = t*B + b_base + b_local
    const int tr0 = ld_row;
    const int tr1 = ld_row + 64;
    const float* rowA0 = A + (size_t)((tr0 & 15) * B + b_base + (tr0 >> 4)) * K;
    const float* rowA1 = A + (size_t)((tr1 & 15) * B + b_base + (tr1 >> 4)) * K;
    const float* rowW  = Wb + (size_t)ld_row * K;

    float4 rA0, rA1, rW;

    // STS of the register-held tile into stage S
#define STS_TILE(S)                                                         \
    {                                                                       \
        float* as_ = (S);                                                   \
        float* ws_ = (S) + BK * BM;                                         \
        as_[(ld_col + 0) * BM + tr0] = rA0.x;                               \
        as_[(ld_col + 1) * BM + tr0] = rA0.y;                               \
        as_[(ld_col + 2) * BM + tr0] = rA0.z;                               \
        as_[(ld_col + 3) * BM + tr0] = rA0.w;                               \
        as_[(ld_col + 0) * BM + tr1] = rA1.x;                               \
        as_[(ld_col + 1) * BM + tr1] = rA1.y;                               \
        as_[(ld_col + 2) * BM + tr1] = rA1.z;                               \
        as_[(ld_col + 3) * BM + tr1] = rA1.w;                               \
        ws_[(ld_col + 0) * BN + ld_row] = rW.x;                             \
        ws_[(ld_col + 1) * BN + ld_row] = rW.y;                             \
        ws_[(ld_col + 2) * BN + ld_row] = rW.z;                             \
        ws_[(ld_col + 3) * BN + ld_row] = rW.w;                             \
    }

    // one GEMM iteration: prefetch tile I+2, compute stage CUR, STS -> NXT
#define GEMM_ITER(I, CUR, NXT)                                              \
    {                                                                       \
        const int k0_ = (I) * BK;                                           \
        const bool has_pf_ = (I) + 2 < niter;                               \
        if (has_pf_) {                                                      \
            const int kn_ = ((I) + 2) * BK + ld_col;                        \
            rA0 = *reinterpret_cast<const float4*>(rowA0 + kn_);            \
            rA1 = *reinterpret_cast<const float4*>(rowA1 + kn_);            \
            rW  = *reinterpret_cast<const float4*>(rowW + kn_);             \
        }                                                                   \
        int fold_local_ = -1;                                               \
        {                                                                   \
            int next_b_ = ((k0_ / KC) + 1) * KC;                            \
            if (next_b_ <= k0_ + BK)      fold_local_ = next_b_ - k0_ - 1;  \
            else if (k0_ + BK == K)       fold_local_ = BK - 1;             \
        }                                                                   \
        const float* as_ = (CUR);                                           \
        const float* ws_ = (CUR) + BK * BM;                                 \
        _Pragma("unroll")                                                   \
        for (int k = 0; k < BK; k++) {                                      \
            const ulonglong2* As2_ = reinterpret_cast<const ulonglong2*>(   \
                as_ + k * BM + trow * 8);                                   \
            ulonglong2 al_ = As2_[0];                                       \
            ulonglong2 ah_ = As2_[1];                                       \
            unsigned long long ap_[4] = {al_.x, al_.y, ah_.x, ah_.y};       \
            const float4* Ws4_ =                                            \
                reinterpret_cast<const float4*>(ws_ + k * BN);              \
            float4 w_ = Ws4_[tcol];                                         \
            unsigned long long wp_[TN];                                     \
            PACK_DUP_F32(wp_[0], w_.x);                                     \
            PACK_DUP_F32(wp_[1], w_.y);                                     \
            PACK_DUP_F32(wp_[2], w_.z);                                     \
            PACK_DUP_F32(wp_[3], w_.w);                                     \
            _Pragma("unroll")                                               \
            for (int i = 0; i < 4; i++)                                     \
                _Pragma("unroll")                                           \
                for (int j = 0; j < TN; j++)                                \
                    FMA_F32X2(cur[i][j], ap_[i], wp_[j], cur[i][j]);        \
            if (k == fold_local_) {                                         \
                _Pragma("unroll")                                           \
                for (int i = 0; i < 4; i++)                                 \
                    _Pragma("unroll")                                       \
                    for (int j = 0; j < TN; j++) {                          \
                        ADD_F32X2_(tot[i][j], tot[i][j], cur[i][j]);        \
                        cur[i][j] = 0ull;                                   \
                    }                                                       \
            }                                                               \
        }                                                                   \
        if (has_pf_) STS_TILE(NXT);                                         \
    }

    const int niter = K / BK;   // 64

    // ---- prologue: fill stages 0 and 1 ----
    rA0 = *reinterpret_cast<const float4*>(rowA0 + ld_col);
    rA1 = *reinterpret_cast<const float4*>(rowA1 + ld_col);
    rW  = *reinterpret_cast<const float4*>(rowW + ld_col);
    STS_TILE(st0);
    rA0 = *reinterpret_cast<const float4*>(rowA0 + BK + ld_col);
    rA1 = *reinterpret_cast<const float4*>(rowA1 + BK + ld_col);
    rW  = *reinterpret_cast<const float4*>(rowW + BK + ld_col);
    STS_TILE(st1);
    __syncthreads();

    // ---- main loop: 4-stage ring, sync after every odd iteration ----
    for (int i = 0; i < niter; i += 4) {
        GEMM_ITER(i + 0, st0, st2);
        GEMM_ITER(i + 1, st1, st3);
        __syncthreads();
        GEMM_ITER(i + 2, st2, st0);
        GEMM_ITER(i + 3, st3, st1);
        __syncthreads();
    }

    // ------------------------- fused epilogue -------------------------
    // thread rows: tile rows trow*8 + r (r=0..7)
    //   b_local = trow>>1, t = (trow&1)*8 + r
    const int n0 = bcol * BN + tcol * TN;
    const int b  = b_base + (trow >> 1);
    const bool upper = (trow & 1);

    // unpack + bias (identical scalar fp32 add as rounds 4-15)
    float v[8][TN];
    #pragma unroll
    for (int i = 0; i < 4; i++) {
        float lo[TN], hi[TN];
        #pragma unroll
        for (int j = 0; j < TN; j++)
            UNPACK_F32X2_(lo[j], hi[j], tot[i][j]);
        #pragma unroll
        for (int j = 0; j < TN; j++) {
            v[2 * i + 0][j] = lo[j] + bias[n0 + j];
            v[2 * i + 1][j] = hi[j] + bias[n0 + j];
        }
    }

    // LIF scan, ascending t. Pass 1: scan from 0 (valid for lower half).
    float sp[8][TN];
    float fin[TN];
    #pragma unroll
    for (int j = 0; j < TN; j++) {
        float memb = 0.0f;
        #pragma unroll
        for (int r = 0; r < 8; r++) {
            memb += v[r][j];
            float s = (memb > 1.0f) ? 1.0f : 0.0f;
            sp[r][j] = s;
            memb = (s > 0.0f) ? 0.0f : memb;
        }
        fin[j] = memb;
    }
    // hand membrane from lower half (lane l) to upper half (lane l+16)
    #pragma unroll
    for (int j = 0; j < TN; j++)
        fin[j] = __shfl_up_sync(0xffffffffu, fin[j], 16);
    if (upper) {
        #pragma unroll
        for (int j = 0; j < TN; j++) {
            float memb = fin[j];
            #pragma unroll
            for (int r = 0; r < 8; r++) {
                memb += v[r][j];
                float s = (memb > 1.0f) ? 1.0f : 0.0f;
                sp[r][j] = s;
                memb = (s > 0.0f) ? 0.0f : memb;
            }
        }
    }

    // store spikes: row m = t*B + b, t = upper*8 + r
    #pragma unroll
    for (int r = 0; r < 8; r++) {
        const int t = (upper ? 8 : 0) + r;
        float* crow = spikes + (size_t)(t * B + b) * N + n0;
        float4 o;
        o.x = sp[r][0];
        o.y = sp[r][1];
        o.z = sp[r][2];
        o.w = sp[r][3];
        *reinterpret_cast<float4*>(crow) = o;
    }
}

// ----------------------------- launch --------------------------------------
extern "C" void kernel_launch(void* const* d_in, const int* in_sizes, int n_in,
                              void* d_out, int out_size) {
    const float* x    = (const float*)d_in[0];  // [T*B, F_IN]
    const float* w    = (const float*)d_in[1];  // [F_OUT, F_IN]
    const float* bias = (const float*)d_in[2];  // [F_OUT]

    const int F_OUT = in_sizes[2];                 // 1024
    const int F_IN  = in_sizes[1] / F_OUT;         // 1024
    const int M     = in_sizes[0] / F_IN;          // 32768
    const int B     = M / T_STEPS;                 // 2048

    cudaFuncSetAttribute(spikelinear_fused_kernel,
                         cudaFuncAttributeMaxDynamicSharedMemorySize,
                         SMEM_BYTES);

    dim3 grid(F_OUT / BN, B / (BM / T_STEPS));     // (16, 256)
    spikelinear_fused_kernel<<<grid, 256, SMEM_BYTES>>>(x, w, bias,
                                                        (float*)d_out,
                                                        B, F_OUT, F_IN);
}

// round 17
// speedup vs baseline: 1.0520x; 1.0007x over previous
#include <cuda_runtime.h>
#include <cuda_bf16.h>
#include <cstdint>

// ---------------------------------------------------------------------------
// SpikeLinear: out = x @ W^T + bias, then LIF scan (T=16), fully fused.
//
// FINAL KERNEL (rounds 10/13/14/16: 1437.8/1438.2/1439.3/1438.2 us;
// 92% of the FFMA2 rt=3 issue bound).
//
// Design decisions, each validated by an isolated experiment:
//  - Numerics: replicate the reference's XLA:CPU/Eigen gebp accumulation
//    (kc=248 panel restart, ascending-k fmaf, ascending panel folds at
//    k_end = 248/496/744/992/1024, fp32 bias add, ascending-t LIF scan)
//    -> rel_err 0.000970705, bit-stable across 13 benches. ANY reordering
//    (tensor cores, exact fp64 accumulation) decorrelates the binary spike
//    flips from the reference and fails the 1e-3 threshold (rounds 1-3).
//  - fma.rn.f32x2 (FFMA2): 2 IEEE fp32 RN FMAs/instr, bit-identical per
//    component, ptxas never auto-emits it. rt=3 from RF banking (3 distinct
//    64-bit operand pairs) => 85.3 FMA/cyc/SM floor (round 5).
//  - BK=16, 4-stage smem ring, one __syncthreads per 2 iterations
//    (rounds 6/8/9/10: BK=32 regresses ~20% via LDG/STS burst serialization;
//    further barrier reduction gains only ~2.5 us).
//  - LIF scan fused into the GEMM epilogue via t-major M-tile remap +
//    half-warp shuffle handoff (round 7: -37 us, kills the 256 MB
//    intermediate round-trip).
//  - W stays fp32 in shared; {w,w} packs ride the ~90%-idle ALU pipe
//    (round 12: pre-duplicated u64 W doubles LDS wavefronts and saturates
//    the 128 B/cyc smem crossbar -> 2x regression).
//  - Accumulators in registers at occ 2 (round 11: occ 3 net worse;
//    round 15: tot-in-shared at occ 2 net worse, -5%).
// ---------------------------------------------------------------------------

#define KC 248               // Eigen panel width (validated round 4)

#define BM 128
#define BN 64
#define BK 16
#define TN 4
#define T_STEPS 16

#define STAGE_FLOATS (BK * (BM + BN))          // 3072 floats = 12 KB
#define SMEM_BYTES   (4 * STAGE_FLOATS * 4)    // 48 KB

#define FMA_F32X2(d, a, b, c) \
    asm("fma.rn.f32x2 %0, %1, %2, %3;" : "=l"(d) : "l"(a), "l"(b), "l"(c))
#define ADD_F32X2_(d, a, b) \
    asm("add.rn.f32x2 %0, %1, %2;" : "=l"(d) : "l"(a), "l"(b))
#define PACK_DUP_F32(d, x) \
    asm("mov.b64 %0, {%1, %2};" : "=l"(d) : "f"(x), "f"(x))
#define UNPACK_F32X2_(lo, hi, p) \
    asm("mov.b64 {%0, %1}, %2;" : "=f"(lo), "=f"(hi) : "l"(p))

__global__ __launch_bounds__(256, 2)
void spikelinear_fused_kernel(const float* __restrict__ A,
                              const float* __restrict__ W,
                              const float* __restrict__ bias,
                              float* __restrict__ spikes,
                              int B, int N, int K) {
    extern __shared__ float smem[];
    // stage s: As = smem + s*STAGE_FLOATS            ([BK][BM])
    //          Ws = smem + s*STAGE_FLOATS + BK*BM    ([BK][BN])
    float* const st0 = smem + 0 * STAGE_FLOATS;
    float* const st1 = smem + 1 * STAGE_FLOATS;
    float* const st2 = smem + 2 * STAGE_FLOATS;
    float* const st3 = smem + 3 * STAGE_FLOATS;

    const int tid    = threadIdx.x;          // 0..255
    const int b_tile = blockIdx.y;            // batch tile (8 b's)
    const int bcol   = blockIdx.x;            // N tile

    const int tcol = tid % (BN / TN);          // 0..15
    const int trow = tid / (BN / TN);          // 0..15

    const int b_base = b_tile * (BM / T_STEPS);   // 8 b's per block

    // packed accumulators: [m-pair 0..3][n 0..3]
    unsigned long long cur[4][TN];
    unsigned long long tot[4][TN];
    #pragma unroll
    for (int i = 0; i < 4; i++)
        #pragma unroll
        for (int j = 0; j < TN; j++) { cur[i][j] = 0ull; tot[i][j] = 0ull; }

    const float* Wb = W + (size_t)bcol * BN * K;

    // loader mapping (BK=16): A tile 128x16 -> 2 float4/thread,
    // W tile 64x16 -> 1 float4/thread.
    const int ld_row = tid / 4;               // 0..63
    const int ld_col = (tid % 4) * 4;         // 0,4,8,12

    // tile_row -> global m: b_local = row>>4, t = row&15, m = t*B + b_base + b_local
    const int tr0 = ld_row;
    const int tr1 = ld_row + 64;
    const float* rowA0 = A + (size_t)((tr0 & 15) * B + b_base + (tr0 >> 4)) * K;
    const float* rowA1 = A + (size_t)((tr1 & 15) * B + b_base + (tr1 >> 4)) * K;
    const float* rowW  = Wb + (size_t)ld_row * K;

    float4 rA0, rA1, rW;

    // STS of the register-held tile into stage S
#define STS_TILE(S)                                                         \
    {                                                                       \
        float* as_ = (S);                                                   \
        float* ws_ = (S) + BK * BM;                                         \
        as_[(ld_col + 0) * BM + tr0] = rA0.x;                               \
        as_[(ld_col + 1) * BM + tr0] = rA0.y;                               \
        as_[(ld_col + 2) * BM + tr0] = rA0.z;                               \
        as_[(ld_col + 3) * BM + tr0] = rA0.w;                               \
        as_[(ld_col + 0) * BM + tr1] = rA1.x;                               \
        as_[(ld_col + 1) * BM + tr1] = rA1.y;                               \
        as_[(ld_col + 2) * BM + tr1] = rA1.z;                               \
        as_[(ld_col + 3) * BM + tr1] = rA1.w;                               \
        ws_[(ld_col + 0) * BN + ld_row] = rW.x;                             \
        ws_[(ld_col + 1) * BN + ld_row] = rW.y;                             \
        ws_[(ld_col + 2) * BN + ld_row] = rW.z;                             \
        ws_[(ld_col + 3) * BN + ld_row] = rW.w;                             \
    }

    // one GEMM iteration: prefetch tile I+2, compute stage CUR, STS -> NXT
#define GEMM_ITER(I, CUR, NXT)                                              \
    {                                                                       \
        const int k0_ = (I) * BK;                                           \
        const bool has_pf_ = (I) + 2 < niter;                               \
        if (has_pf_) {                                                      \
            const int kn_ = ((I) + 2) * BK + ld_col;                        \
            rA0 = *reinterpret_cast<const float4*>(rowA0 + kn_);            \
            rA1 = *reinterpret_cast<const float4*>(rowA1 + kn_);            \
            rW  = *reinterpret_cast<const float4*>(rowW + kn_);             \
        }                                                                   \
        int fold_local_ = -1;                                               \
        {                                                                   \
            int next_b_ = ((k0_ / KC) + 1) * KC;                            \
            if (next_b_ <= k0_ + BK)      fold_local_ = next_b_ - k0_ - 1;  \
            else if (k0_ + BK == K)       fold_local_ = BK - 1;             \
        }                                                                   \
        const float* as_ = (CUR);                                           \
        const float* ws_ = (CUR) + BK * BM;                                 \
        _Pragma("unroll")                                                   \
        for (int k = 0; k < BK; k++) {                                      \
            const ulonglong2* As2_ = reinterpret_cast<const ulonglong2*>(   \
                as_ + k * BM + trow * 8);                                   \
            ulonglong2 al_ = As2_[0];                                       \
            ulonglong2 ah_ = As2_[1];                                       \
            unsigned long long ap_[4] = {al_.x, al_.y, ah_.x, ah_.y};       \
            const float4* Ws4_ =                                            \
                reinterpret_cast<const float4*>(ws_ + k * BN);              \
            float4 w_ = Ws4_[tcol];                                         \
            unsigned long long wp_[TN];                                     \
            PACK_DUP_F32(wp_[0], w_.x);                                     \
            PACK_DUP_F32(wp_[1], w_.y);                                     \
            PACK_DUP_F32(wp_[2], w_.z);                                     \
            PACK_DUP_F32(wp_[3], w_.w);                                     \
            _Pragma("unroll")                                               \
            for (int i = 0; i < 4; i++)                                     \
                _Pragma("unroll")                                           \
                for (int j = 0; j < TN; j++)                                \
                    FMA_F32X2(cur[i][j], ap_[i], wp_[j], cur[i][j]);        \
            if (k == fold_local_) {                                         \
                _Pragma("unroll")                                           \
                for (int i = 0; i < 4; i++)                                 \
                    _Pragma("unroll")                                       \
                    for (int j = 0; j < TN; j++) {                          \
                        ADD_F32X2_(tot[i][j], tot[i][j], cur[i][j]);        \
                        cur[i][j] = 0ull;                                   \
                    }                                                       \
            }                                                               \
        }                                                                   \
        if (has_pf_) STS_TILE(NXT);                                         \
    }

    const int niter = K / BK;   // 64

    // ---- prologue: fill stages 0 and 1 ----
    rA0 = *reinterpret_cast<const float4*>(rowA0 + ld_col);
    rA1 = *reinterpret_cast<const float4*>(rowA1 + ld_col);
    rW  = *reinterpret_cast<const float4*>(rowW + ld_col);
    STS_TILE(st0);
    rA0 = *reinterpret_cast<const float4*>(rowA0 + BK + ld_col);
    rA1 = *reinterpret_cast<const float4*>(rowA1 + BK + ld_col);
    rW  = *reinterpret_cast<const float4*>(rowW + BK + ld_col);
    STS_TILE(st1);
    __syncthreads();

    // ---- main loop: 4-stage ring, sync after every odd iteration ----
    for (int i = 0; i < niter; i += 4) {
        GEMM_ITER(i + 0, st0, st2);
        GEMM_ITER(i + 1, st1, st3);
        __syncthreads();
        GEMM_ITER(i + 2, st2, st0);
        GEMM_ITER(i + 3, st3, st1);
        __syncthreads();
    }

    // ------------------------- fused epilogue -------------------------
    // thread rows: tile rows trow*8 + r (r=0..7)
    //   b_local = trow>>1, t = (trow&1)*8 + r
    const int n0 = bcol * BN + tcol * TN;
    const int b  = b_base + (trow >> 1);
    const bool upper = (trow & 1);

    // unpack + bias (identical scalar fp32 add as rounds 4-16)
    float v[8][TN];
    #pragma unroll
    for (int i = 0; i < 4; i++) {
        float lo[TN], hi[TN];
        #pragma unroll
        for (int j = 0; j < TN; j++)
            UNPACK_F32X2_(lo[j], hi[j], tot[i][j]);
        #pragma unroll
        for (int j = 0; j < TN; j++) {
            v[2 * i + 0][j] = lo[j] + bias[n0 + j];
            v[2 * i + 1][j] = hi[j] + bias[n0 + j];
        }
    }

    // LIF scan, ascending t. Pass 1: scan from 0 (valid for lower half).
    float sp[8][TN];
    float fin[TN];
    #pragma unroll
    for (int j = 0; j < TN; j++) {
        float memb = 0.0f;
        #pragma unroll
        for (int r = 0; r < 8; r++) {
            memb += v[r][j];
            float s = (memb > 1.0f) ? 1.0f : 0.0f;
            sp[r][j] = s;
            memb = (s > 0.0f) ? 0.0f : memb;
        }
        fin[j] = memb;
    }
    // hand membrane from lower half (lane l) to upper half (lane l+16)
    #pragma unroll
    for (int j = 0; j < TN; j++)
        fin[j] = __shfl_up_sync(0xffffffffu, fin[j], 16);
    if (upper) {
        #pragma unroll
        for (int j = 0; j < TN; j++) {
            float memb = fin[j];
            #pragma unroll
            for (int r = 0; r < 8; r++) {
                memb += v[r][j];
                float s = (memb > 1.0f) ? 1.0f : 0.0f;
                sp[r][j] = s;
                memb = (s > 0.0f) ? 0.0f : memb;
            }
        }
    }

    // store spikes: row m = t*B + b, t = upper*8 + r
    #pragma unroll
    for (int r = 0; r < 8; r++) {
        const int t = (upper ? 8 : 0) + r;
        float* crow = spikes + (size_t)(t * B + b) * N + n0;
        float4 o;
        o.x = sp[r][0];
        o.y = sp[r][1];
        o.z = sp[r][2];
        o.w = sp[r][3];
        *reinterpret_cast<float4*>(crow) = o;
    }
}

// ----------------------------- launch --------------------------------------
extern "C" void kernel_launch(void* const* d_in, const int* in_sizes, int n_in,
                              void* d_out, int out_size) {
    const float* x    = (const float*)d_in[0];  // [T*B, F_IN]
    const float* w    = (const float*)d_in[1];  // [F_OUT, F_IN]
    const float* bias = (const float*)d_in[2];  // [F_OUT]

    const int F_OUT = in_sizes[2];                 // 1024
    const int F_IN  = in_sizes[1] / F_OUT;         // 1024
    const int M     = in_sizes[0] / F_IN;          // 32768
    const int B     = M / T_STEPS;                 // 2048

    cudaFuncSetAttribute(spikelinear_fused_kernel,
                         cudaFuncAttributeMaxDynamicSharedMemorySize,
                         SMEM_BYTES);

    dim3 grid(F_OUT / BN, B / (BM / T_STEPS));     // (16, 256)
    spikelinear_fused_kernel<<<grid, 256, SMEM_BYTES>>>(x, w, bias,
                                                        (float*)d_out,
                                                        B, F_OUT, F_IN);
}